// round 15
// baseline (speedup 1.0000x reference)
#include <cuda_runtime.h>
#include <cuda_fp16.h>
#include <cuda_bf16.h>
#include <cstdint>

#define N_NODES 50000
#define N_EDGES 1600000
#define IN_F    256
#define OUT_F   128
#define N_REL   500

// ---------------- scratch (device globals; no allocations allowed) ----------
__device__ __half g_Whh[(size_t)N_NODES * OUT_F]; // 12.8 MB fp16 gather table
__device__ float  g_si[N_NODES];
__device__ float  g_sj[N_NODES];
__device__ float  g_srel[N_REL];
__device__ int    g_cnt[N_NODES];
__device__ int    g_off[N_NODES + 1];
__device__ int    g_cur[N_NODES];
__device__ unsigned g_pc[N_EDGES];                // (et<<16)|col in CSR order
// W split into bf16 hi/lo planes, stored transposed [n][k]
__device__ __nv_bfloat16 g_Bh[OUT_F * IN_F];
__device__ __nv_bfloat16 g_Bl[OUT_F * IN_F];

// ================= helpers ====================================================
__device__ __forceinline__ uint32_t smem_u32(const void* p) {
    uint32_t a;
    asm("{ .reg .u64 t; cvta.to.shared.u64 t, %1; cvt.u32.u64 %0, t; }"
        : "=r"(a) : "l"(p));
    return a;
}
__device__ __forceinline__ void ldsm4(uint32_t* r, uint32_t a) {
    asm volatile("ldmatrix.sync.aligned.m8n8.x4.shared.b16 {%0,%1,%2,%3}, [%4];"
                 : "=r"(r[0]), "=r"(r[1]), "=r"(r[2]), "=r"(r[3]) : "r"(a));
}
__device__ __forceinline__ void mma_bf16(float* c, const uint32_t* a,
                                         const uint32_t* b) {
    asm volatile(
        "mma.sync.aligned.m16n8k16.row.col.f32.bf16.bf16.f32 "
        "{%0,%1,%2,%3},{%4,%5,%6,%7},{%8,%9},{%0,%1,%2,%3};"
        : "+f"(c[0]), "+f"(c[1]), "+f"(c[2]), "+f"(c[3])
        : "r"(a[0]), "r"(a[1]), "r"(a[2]), "r"(a[3]), "r"(b[0]), "r"(b[1]));
}

// ---------------- prep: split W into bf16 hi/lo, transposed [n][k] -----------
__global__ void prep_b_kernel(const float* __restrict__ W) {
    int id = blockIdx.x * blockDim.x + threadIdx.x;
    if (id >= OUT_F * IN_F) return;
    int n = id >> 8;
    int k = id & 255;
    float v = W[(size_t)k * OUT_F + n];
    __nv_bfloat16 hb = __float2bfloat16_rn(v);
    float lo = v - __bfloat162float(hb);
    g_Bh[id] = hb;
    g_Bl[id] = __float2bfloat16_rn(lo);
}

// ---------------- zero counters ---------------------------------------------
__global__ void zero_cnt_kernel() {
    int i = blockIdx.x * blockDim.x + threadIdx.x;
    if (i < N_NODES) g_cnt[i] = 0;
}

// ---------------- bf16 tensor-core GEMM (2-split) + fused epilogue -----------
#define LDA 40   // bf16 leading dim: 80B rows -> conflict-free LDSM phases
__global__ __launch_bounds__(256) void gemm_kernel(const float* __restrict__ A,
                                                   const float* __restrict__ avec,
                                                   int M) {
    __shared__ __align__(16) __nv_bfloat16 sAh[128 * LDA];
    __shared__ __align__(16) __nv_bfloat16 sAl[128 * LDA];
    __shared__ __align__(16) __nv_bfloat16 sBh[128 * LDA];
    __shared__ __align__(16) __nv_bfloat16 sBl[128 * LDA];
    __shared__ float s_a[256];
    __shared__ float s_si[128], s_sj[128];

    int t = threadIdx.x;
    int lane = t & 31;
    int w = t >> 5;
    int wm = (w & 3) * 32;
    int wn = (w >> 2) * 64;
    int block_m = blockIdx.x * 128;

    if (t < 128) {
        s_si[t] = 0.f; s_sj[t] = 0.f;
        s_a[t] = avec[t]; s_a[128 + t] = avec[128 + t];
    }

    float acc[2][8][4];
#pragma unroll
    for (int i = 0; i < 2; i++)
#pragma unroll
        for (int j = 0; j < 8; j++)
#pragma unroll
            for (int r = 0; r < 4; r++) acc[i][j][r] = 0.f;

    uint32_t bAh = smem_u32(sAh), bAl = smem_u32(sAl);
    uint32_t bBh = smem_u32(sBh), bBl = smem_u32(sBl);
    int r8 = lane & 7, mi = lane >> 3;

    float4 pa[4];
    uint4 pbh[2], pbl[2];

    auto load_regs = [&](int c) {
        int k0 = c * 32;
#pragma unroll
        for (int s = 0; s < 4; s++) {
            int idx = t + s * 256;
            int row = idx >> 3;
            int q = idx & 7;
            int grow = block_m + row;
            if (grow >= M) grow = M - 1;
            pa[s] = *(const float4*)(A + (size_t)grow * IN_F + k0 + q * 4);
        }
#pragma unroll
        for (int s = 0; s < 2; s++) {
            int idx = t + s * 256;
            int n = idx >> 2;
            int q = idx & 3;
            pbh[s] = *(const uint4*)(g_Bh + (size_t)n * IN_F + k0 + q * 8);
            pbl[s] = *(const uint4*)(g_Bl + (size_t)n * IN_F + k0 + q * 8);
        }
    };

    load_regs(0);

    for (int c = 0; c < 8; c++) {
#pragma unroll
        for (int s = 0; s < 4; s++) {
            int idx = t + s * 256;
            int row = idx >> 3;
            int q = idx & 7;
            float vv[4] = {pa[s].x, pa[s].y, pa[s].z, pa[s].w};
            __nv_bfloat16 hb[4], lb[4];
#pragma unroll
            for (int j = 0; j < 4; j++) {
                hb[j] = __float2bfloat16_rn(vv[j]);
                lb[j] = __float2bfloat16_rn(vv[j] - __bfloat162float(hb[j]));
            }
            *(uint2*)(sAh + row * LDA + q * 4) = *(uint2*)hb;
            *(uint2*)(sAl + row * LDA + q * 4) = *(uint2*)lb;
        }
#pragma unroll
        for (int s = 0; s < 2; s++) {
            int idx = t + s * 256;
            int n = idx >> 2;
            int q = idx & 3;
            *(uint4*)(sBh + n * LDA + q * 8) = pbh[s];
            *(uint4*)(sBl + n * LDA + q * 8) = pbl[s];
        }
        __syncthreads();

        if (c < 7) load_regs(c + 1);

#pragma unroll
        for (int ks = 0; ks < 2; ks++) {
            uint32_t ahi[2][4], alo[2][4];
#pragma unroll
            for (int ms = 0; ms < 2; ms++) {
                uint32_t off =
                    (uint32_t)((wm + ms * 16 + r8 + (mi & 1) * 8) * LDA +
                               ks * 16 + (mi >> 1) * 8) * 2;
                ldsm4(ahi[ms], bAh + off);
                ldsm4(alo[ms], bAl + off);
            }
            uint32_t bhi[8][2], blo[8][2];
#pragma unroll
            for (int np = 0; np < 4; np++) {
                uint32_t off =
                    (uint32_t)((wn + np * 16 + r8 + (mi >> 1) * 8) * LDA +
                               ks * 16 + (mi & 1) * 8) * 2;
                uint32_t tmp[4];
                ldsm4(tmp, bBh + off);
                bhi[np * 2][0] = tmp[0]; bhi[np * 2][1] = tmp[1];
                bhi[np * 2 + 1][0] = tmp[2]; bhi[np * 2 + 1][1] = tmp[3];
                ldsm4(tmp, bBl + off);
                blo[np * 2][0] = tmp[0]; blo[np * 2][1] = tmp[1];
                blo[np * 2 + 1][0] = tmp[2]; blo[np * 2 + 1][1] = tmp[3];
            }
#pragma unroll
            for (int ns = 0; ns < 8; ns++)
#pragma unroll
                for (int ms = 0; ms < 2; ms++) {
                    mma_bf16(acc[ms][ns], ahi[ms], bhi[ns]);
                    mma_bf16(acc[ms][ns], ahi[ms], blo[ns]);
                    mma_bf16(acc[ms][ns], alo[ms], bhi[ns]);
                }
        }
        __syncthreads();
    }

    // ---- epilogue: fp16 stores + fused attention dots ----
#pragma unroll
    for (int ms = 0; ms < 2; ms++) {
        int lr0 = wm + ms * 16 + (lane >> 2);
        int g0 = block_m + lr0;
        int g1 = g0 + 8;
        float psi0 = 0.f, psj0 = 0.f, psi1 = 0.f, psj1 = 0.f;
#pragma unroll
        for (int ns = 0; ns < 8; ns++) {
            int col0 = wn + ns * 8 + 2 * (lane & 3);
            float* cc = acc[ms][ns];
            float ai0 = s_a[col0], ai1 = s_a[col0 + 1];
            float aj0 = s_a[128 + col0], aj1 = s_a[128 + col0 + 1];
            psi0 += cc[0] * ai0 + cc[1] * ai1;
            psj0 += cc[0] * aj0 + cc[1] * aj1;
            psi1 += cc[2] * ai0 + cc[3] * ai1;
            psj1 += cc[2] * aj0 + cc[3] * aj1;
            if (g0 < M)
                *(__half2*)(g_Whh + (size_t)g0 * OUT_F + col0) =
                    __floats2half2_rn(cc[0], cc[1]);
            if (g1 < M)
                *(__half2*)(g_Whh + (size_t)g1 * OUT_F + col0) =
                    __floats2half2_rn(cc[2], cc[3]);
        }
#pragma unroll
        for (int o = 1; o < 4; o <<= 1) {
            psi0 += __shfl_xor_sync(0xffffffffu, psi0, o);
            psj0 += __shfl_xor_sync(0xffffffffu, psj0, o);
            psi1 += __shfl_xor_sync(0xffffffffu, psi1, o);
            psj1 += __shfl_xor_sync(0xffffffffu, psj1, o);
        }
        if ((lane & 3) == 0) {
            atomicAdd(&s_si[lr0], psi0);
            atomicAdd(&s_sj[lr0], psj0);
            atomicAdd(&s_si[lr0 + 8], psi1);
            atomicAdd(&s_sj[lr0 + 8], psj1);
        }
    }
    __syncthreads();
    if (t < 128) {
        int g = block_m + t;
        if (g < M) { g_si[g] = s_si[t]; g_sj[g] = s_sj[t]; }
    }
}

// ---------------- rel_emb dot products (tiny: 500 warps) ---------------------
__global__ void rel_dots_kernel(const float* __restrict__ a,
                                const float* __restrict__ rel_emb) {
    int gw = (blockIdx.x * blockDim.x + threadIdx.x) >> 5;
    int lane = threadIdx.x & 31;
    if (gw >= N_REL) return;
    float4 v = ((const float4*)rel_emb)[(size_t)gw * 32 + lane];
    float4 ar = ((const float4*)(a + 256))[lane];
    float s = v.x * ar.x + v.y * ar.y + v.z * ar.z + v.w * ar.w;
#pragma unroll
    for (int o = 16; o; o >>= 1) s += __shfl_xor_sync(0xffffffffu, s, o);
    if (lane == 0) g_srel[gw] = s;
}

// ---------------- CSR build --------------------------------------------------
#define NE4 (N_EDGES / 4)
#define QTR (NE4 / 4)
__global__ void count_kernel(const int* __restrict__ rows) {
    int i = blockIdx.x * blockDim.x + threadIdx.x;
    if (i >= QTR) return;
    const int4* r4 = (const int4*)rows;
    int4 v0 = r4[i];
    int4 v1 = r4[i + QTR];
    int4 v2 = r4[i + 2 * QTR];
    int4 v3 = r4[i + 3 * QTR];
    atomicAdd(&g_cnt[v0.x], 1); atomicAdd(&g_cnt[v0.y], 1);
    atomicAdd(&g_cnt[v0.z], 1); atomicAdd(&g_cnt[v0.w], 1);
    atomicAdd(&g_cnt[v1.x], 1); atomicAdd(&g_cnt[v1.y], 1);
    atomicAdd(&g_cnt[v1.z], 1); atomicAdd(&g_cnt[v1.w], 1);
    atomicAdd(&g_cnt[v2.x], 1); atomicAdd(&g_cnt[v2.y], 1);
    atomicAdd(&g_cnt[v2.z], 1); atomicAdd(&g_cnt[v2.w], 1);
    atomicAdd(&g_cnt[v3.x], 1); atomicAdd(&g_cnt[v3.y], 1);
    atomicAdd(&g_cnt[v3.z], 1); atomicAdd(&g_cnt[v3.w], 1);
}

__global__ void scan_kernel() {
    __shared__ int part[1024];
    const int C = (N_NODES + 1023) / 1024;  // 49
    int t = threadIdx.x;
    int base = t * C;
    int s = 0;
    for (int i = 0; i < C; i++) {
        int idx = base + i;
        if (idx < N_NODES) s += g_cnt[idx];
    }
    part[t] = s;
    __syncthreads();
    for (int d = 1; d < 1024; d <<= 1) {
        int v = (t >= d) ? part[t - d] : 0;
        __syncthreads();
        part[t] += v;
        __syncthreads();
    }
    int run = part[t] - s;
    for (int i = 0; i < C; i++) {
        int idx = base + i;
        if (idx < N_NODES) {
            g_off[idx] = run;
            g_cur[idx] = run;
            run += g_cnt[idx];
        }
    }
    if (t == 1023) g_off[N_NODES] = part[1023];
}

// topology-only scatter: packs (et<<16)|col into CSR slots (4 edges/thread)
__global__ void scatter_kernel(const int* __restrict__ rows,
                               const int* __restrict__ cols,
                               const int* __restrict__ et) {
    int i = blockIdx.x * blockDim.x + threadIdx.x;
    if (i >= NE4) return;
    int4 r = ((const int4*)rows)[i];
    int4 c = ((const int4*)cols)[i];
    int4 tt = ((const int4*)et)[i];
    int rr[4] = {r.x, r.y, r.z, r.w};
    int cc[4] = {c.x, c.y, c.z, c.w};
    int ee[4] = {tt.x, tt.y, tt.z, tt.w};
#pragma unroll
    for (int j = 0; j < 4; j++) {
        int p = atomicAdd(&g_cur[rr[j]], 1);
        g_pc[p] = ((unsigned)ee[j] << 16) | (unsigned)cc[j];
    }
}

// ---------------- aggregation: R7 form (inline weights) ----------------------
// global max skipped: softmax shift-invariant up to eps, effect <= 1e-9 rel.
__global__ void agg_kernel(float* __restrict__ out) {
    int warp = (blockIdx.x * blockDim.x + threadIdx.x) >> 5;
    int lane = threadIdx.x & 31;
    if (warp >= N_NODES) return;
    int beg = g_off[warp];
    int end = g_off[warp + 1];
    float si_n = g_si[warp];

    float4 acc = make_float4(0.f, 0.f, 0.f, 0.f);
    float sumw = 0.f;

    for (int k = beg; k < end; k += 32) {
        int idx = k + lane;
        unsigned pc = 0u;
        float wv = 0.f;
        if (idx < end) {
            pc = g_pc[idx];
            float x = si_n + g_sj[pc & 0xFFFFu] + g_srel[pc >> 16];
            x = x > 0.f ? x : 0.2f * x;       // leaky_relu
            wv = __expf(x);
        }
        int m = end - k;
        if (m > 32) m = 32;
#pragma unroll 4
        for (int j = 0; j < m; j++) {
            float wj = __shfl_sync(0xffffffffu, wv, j);
            int   cj = (int)(__shfl_sync(0xffffffffu, pc, j) & 0xFFFFu);
            uint2 raw = *((const uint2*)(g_Whh + (size_t)cj * OUT_F) + lane);
            float2 f0 = __half22float2(*(const __half2*)&raw.x);
            float2 f1 = __half22float2(*(const __half2*)&raw.y);
            acc.x = fmaf(wj, f0.x, acc.x);
            acc.y = fmaf(wj, f0.y, acc.y);
            acc.z = fmaf(wj, f1.x, acc.z);
            acc.w = fmaf(wj, f1.y, acc.w);
            sumw += wj;
        }
    }
    float inv = 1.f / (sumw + 1e-10f);
    float4 o;
    o.x = acc.x * inv; o.y = acc.y * inv; o.z = acc.z * inv; o.w = acc.w * inv;
    o.x = o.x > 0.f ? o.x : expf(o.x) - 1.f;
    o.y = o.y > 0.f ? o.y : expf(o.y) - 1.f;
    o.z = o.z > 0.f ? o.z : expf(o.z) - 1.f;
    o.w = o.w > 0.f ? o.w : expf(o.w) - 1.f;
    ((float4*)out)[(size_t)warp * 32 + lane] = o;
}

// ---------------- launch: R14 graph + DUPLICATED agg (timing instrument) -----
// agg is idempotent (reads g_*, writes out with identical values), so running
// it twice is correct and deterministic; the dur_us delta vs R14 measures one
// agg execution exactly. gemm kept as 4th launch for ncu stability check.
extern "C" void kernel_launch(void* const* d_in, const int* in_sizes, int n_in,
                              void* d_out, int out_size) {
    const float* h    = (const float*)d_in[0];
    const int*   rows = (const int*)d_in[1];
    const int*   cols = (const int*)d_in[2];
    const int*   et   = (const int*)d_in[3];
    const float* W    = (const float*)d_in[4];
    const float* rel  = (const float*)d_in[5];
    const float* a    = (const float*)d_in[6];
    float* out = (float*)d_out;

    static cudaStream_t s1 = nullptr, s2 = nullptr;
    static cudaEvent_t ef1, ef2, ej1, ej2;
    if (!s1) {
        cudaStreamCreateWithFlags(&s1, cudaStreamNonBlocking);
        cudaStreamCreateWithFlags(&s2, cudaStreamNonBlocking);
        cudaEventCreateWithFlags(&ef1, cudaEventDisableTiming);
        cudaEventCreateWithFlags(&ef2, cudaEventDisableTiming);
        cudaEventCreateWithFlags(&ej1, cudaEventDisableTiming);
        cudaEventCreateWithFlags(&ej2, cudaEventDisableTiming);
    }

    cudaEventRecord(ef1, 0);
    cudaStreamWaitEvent(s1, ef1, 0);
    cudaEventRecord(ef2, 0);
    cudaStreamWaitEvent(s2, ef2, 0);

    // launches 1-2: side chain 1 head
    zero_cnt_kernel<<<(N_NODES + 255) / 256, 256, 0, s1>>>();
    count_kernel<<<(QTR + 255) / 256, 256, 0, s1>>>(rows);

    // launches 3-4: main chain (gemm 4th -> profiled)
    prep_b_kernel<<<(OUT_F * IN_F + 255) / 256, 256>>>(W);
    gemm_kernel<<<(N_NODES + 127) / 128, 256>>>(h, a, N_NODES);

    // launches 5-6: rest of side chain 1
    scan_kernel<<<1, 1024, 0, s1>>>();
    scatter_kernel<<<(NE4 + 255) / 256, 256, 0, s1>>>(rows, cols, et);

    // launch 7: side chain 2
    rel_dots_kernel<<<(N_REL * 32 + 255) / 256, 256, 0, s2>>>(a, rel);

    // join before agg
    cudaEventRecord(ej1, s1);
    cudaStreamWaitEvent(0, ej1, 0);
    cudaEventRecord(ej2, s2);
    cudaStreamWaitEvent(0, ej2, 0);

    // launches 8-9: agg twice (second is the measured duplicate)
    agg_kernel<<<(N_NODES * 32 + 255) / 256, 256>>>(out);
    agg_kernel<<<(N_NODES * 32 + 255) / 256, 256>>>(out);
}

// round 16
// speedup vs baseline: 1.7040x; 1.7040x over previous
#include <cuda_runtime.h>
#include <cuda_fp16.h>
#include <cuda_bf16.h>
#include <cstdint>

#define N_NODES 50000
#define N_EDGES 1600000
#define IN_F    256
#define OUT_F   128
#define N_REL   500

#define SCAN_BLK 512
#define SCAN_NB  ((N_NODES + SCAN_BLK - 1) / SCAN_BLK)   // 98

// ---------------- scratch (device globals; no allocations allowed) ----------
__device__ __half g_Whh[(size_t)N_NODES * OUT_F]; // 12.8 MB fp16 gather table
__device__ float  g_si[N_NODES];
__device__ float  g_sj[N_NODES];
__device__ float  g_srel[N_REL];
__device__ int    g_cnt[N_NODES];                 // zero at load; self-reset
__device__ int    g_bsum[SCAN_NB];
__device__ int    g_boff[SCAN_NB];
__device__ int    g_off[N_NODES + 1];
__device__ int    g_cur[N_NODES];
__device__ unsigned g_pc[N_EDGES];                // (et<<16)|col in CSR order
// W split into bf16 hi/lo planes, stored transposed [n][k]
__device__ __nv_bfloat16 g_Bh[OUT_F * IN_F];
__device__ __nv_bfloat16 g_Bl[OUT_F * IN_F];

// ================= helpers ====================================================
__device__ __forceinline__ uint32_t smem_u32(const void* p) {
    uint32_t a;
    asm("{ .reg .u64 t; cvta.to.shared.u64 t, %1; cvt.u32.u64 %0, t; }"
        : "=r"(a) : "l"(p));
    return a;
}
__device__ __forceinline__ void ldsm4(uint32_t* r, uint32_t a) {
    asm volatile("ldmatrix.sync.aligned.m8n8.x4.shared.b16 {%0,%1,%2,%3}, [%4];"
                 : "=r"(r[0]), "=r"(r[1]), "=r"(r[2]), "=r"(r[3]) : "r"(a));
}
__device__ __forceinline__ void mma_bf16(float* c, const uint32_t* a,
                                         const uint32_t* b) {
    asm volatile(
        "mma.sync.aligned.m16n8k16.row.col.f32.bf16.bf16.f32 "
        "{%0,%1,%2,%3},{%4,%5,%6,%7},{%8,%9},{%0,%1,%2,%3};"
        : "+f"(c[0]), "+f"(c[1]), "+f"(c[2]), "+f"(c[3])
        : "r"(a[0]), "r"(a[1]), "r"(a[2]), "r"(a[3]), "r"(b[0]), "r"(b[1]));
}

// ---------------- prep: split W into bf16 hi/lo, transposed [n][k] -----------
__global__ void prep_b_kernel(const float* __restrict__ W) {
    int id = blockIdx.x * blockDim.x + threadIdx.x;
    if (id >= OUT_F * IN_F) return;
    int n = id >> 8;
    int k = id & 255;
    float v = W[(size_t)k * OUT_F + n];
    __nv_bfloat16 hb = __float2bfloat16_rn(v);
    float lo = v - __bfloat162float(hb);
    g_Bh[id] = hb;
    g_Bl[id] = __float2bfloat16_rn(lo);
}

// ---------------- bf16 tensor-core GEMM (2-split) + fused epilogue -----------
#define LDA 40   // bf16 leading dim: 80B rows -> conflict-free LDSM phases
__global__ __launch_bounds__(256) void gemm_kernel(const float* __restrict__ A,
                                                   const float* __restrict__ avec,
                                                   int M) {
    __shared__ __align__(16) __nv_bfloat16 sAh[128 * LDA];
    __shared__ __align__(16) __nv_bfloat16 sAl[128 * LDA];
    __shared__ __align__(16) __nv_bfloat16 sBh[128 * LDA];
    __shared__ __align__(16) __nv_bfloat16 sBl[128 * LDA];
    __shared__ float s_a[256];
    __shared__ float s_si[128], s_sj[128];

    int t = threadIdx.x;
    int lane = t & 31;
    int w = t >> 5;
    int wm = (w & 3) * 32;
    int wn = (w >> 2) * 64;
    int block_m = blockIdx.x * 128;

    if (t < 128) {
        s_si[t] = 0.f; s_sj[t] = 0.f;
        s_a[t] = avec[t]; s_a[128 + t] = avec[128 + t];
    }

    float acc[2][8][4];
#pragma unroll
    for (int i = 0; i < 2; i++)
#pragma unroll
        for (int j = 0; j < 8; j++)
#pragma unroll
            for (int r = 0; r < 4; r++) acc[i][j][r] = 0.f;

    uint32_t bAh = smem_u32(sAh), bAl = smem_u32(sAl);
    uint32_t bBh = smem_u32(sBh), bBl = smem_u32(sBl);
    int r8 = lane & 7, mi = lane >> 3;

    float4 pa[4];
    uint4 pbh[2], pbl[2];

    auto load_regs = [&](int c) {
        int k0 = c * 32;
#pragma unroll
        for (int s = 0; s < 4; s++) {
            int idx = t + s * 256;
            int row = idx >> 3;
            int q = idx & 7;
            int grow = block_m + row;
            if (grow >= M) grow = M - 1;
            pa[s] = *(const float4*)(A + (size_t)grow * IN_F + k0 + q * 4);
        }
#pragma unroll
        for (int s = 0; s < 2; s++) {
            int idx = t + s * 256;
            int n = idx >> 2;
            int q = idx & 3;
            pbh[s] = *(const uint4*)(g_Bh + (size_t)n * IN_F + k0 + q * 8);
            pbl[s] = *(const uint4*)(g_Bl + (size_t)n * IN_F + k0 + q * 8);
        }
    };

    load_regs(0);

    for (int c = 0; c < 8; c++) {
#pragma unroll
        for (int s = 0; s < 4; s++) {
            int idx = t + s * 256;
            int row = idx >> 3;
            int q = idx & 7;
            float vv[4] = {pa[s].x, pa[s].y, pa[s].z, pa[s].w};
            __nv_bfloat16 hb[4], lb[4];
#pragma unroll
            for (int j = 0; j < 4; j++) {
                hb[j] = __float2bfloat16_rn(vv[j]);
                lb[j] = __float2bfloat16_rn(vv[j] - __bfloat162float(hb[j]));
            }
            *(uint2*)(sAh + row * LDA + q * 4) = *(uint2*)hb;
            *(uint2*)(sAl + row * LDA + q * 4) = *(uint2*)lb;
        }
#pragma unroll
        for (int s = 0; s < 2; s++) {
            int idx = t + s * 256;
            int n = idx >> 2;
            int q = idx & 3;
            *(uint4*)(sBh + n * LDA + q * 8) = pbh[s];
            *(uint4*)(sBl + n * LDA + q * 8) = pbl[s];
        }
        __syncthreads();

        if (c < 7) load_regs(c + 1);

#pragma unroll
        for (int ks = 0; ks < 2; ks++) {
            uint32_t ahi[2][4], alo[2][4];
#pragma unroll
            for (int ms = 0; ms < 2; ms++) {
                uint32_t off =
                    (uint32_t)((wm + ms * 16 + r8 + (mi & 1) * 8) * LDA +
                               ks * 16 + (mi >> 1) * 8) * 2;
                ldsm4(ahi[ms], bAh + off);
                ldsm4(alo[ms], bAl + off);
            }
            uint32_t bhi[8][2], blo[8][2];
#pragma unroll
            for (int np = 0; np < 4; np++) {
                uint32_t off =
                    (uint32_t)((wn + np * 16 + r8 + (mi >> 1) * 8) * LDA +
                               ks * 16 + (mi & 1) * 8) * 2;
                uint32_t tmp[4];
                ldsm4(tmp, bBh + off);
                bhi[np * 2][0] = tmp[0]; bhi[np * 2][1] = tmp[1];
                bhi[np * 2 + 1][0] = tmp[2]; bhi[np * 2 + 1][1] = tmp[3];
                ldsm4(tmp, bBl + off);
                blo[np * 2][0] = tmp[0]; blo[np * 2][1] = tmp[1];
                blo[np * 2 + 1][0] = tmp[2]; blo[np * 2 + 1][1] = tmp[3];
            }
#pragma unroll
            for (int ns = 0; ns < 8; ns++)
#pragma unroll
                for (int ms = 0; ms < 2; ms++) {
                    mma_bf16(acc[ms][ns], ahi[ms], bhi[ns]);
                    mma_bf16(acc[ms][ns], ahi[ms], blo[ns]);
                    mma_bf16(acc[ms][ns], alo[ms], bhi[ns]);
                }
        }
        __syncthreads();
    }

    // ---- epilogue: fp16 stores + fused attention dots ----
#pragma unroll
    for (int ms = 0; ms < 2; ms++) {
        int lr0 = wm + ms * 16 + (lane >> 2);
        int g0 = block_m + lr0;
        int g1 = g0 + 8;
        float psi0 = 0.f, psj0 = 0.f, psi1 = 0.f, psj1 = 0.f;
#pragma unroll
        for (int ns = 0; ns < 8; ns++) {
            int col0 = wn + ns * 8 + 2 * (lane & 3);
            float* cc = acc[ms][ns];
            float ai0 = s_a[col0], ai1 = s_a[col0 + 1];
            float aj0 = s_a[128 + col0], aj1 = s_a[128 + col0 + 1];
            psi0 += cc[0] * ai0 + cc[1] * ai1;
            psj0 += cc[0] * aj0 + cc[1] * aj1;
            psi1 += cc[2] * ai0 + cc[3] * ai1;
            psj1 += cc[2] * aj0 + cc[3] * aj1;
            if (g0 < M)
                *(__half2*)(g_Whh + (size_t)g0 * OUT_F + col0) =
                    __floats2half2_rn(cc[0], cc[1]);
            if (g1 < M)
                *(__half2*)(g_Whh + (size_t)g1 * OUT_F + col0) =
                    __floats2half2_rn(cc[2], cc[3]);
        }
#pragma unroll
        for (int o = 1; o < 4; o <<= 1) {
            psi0 += __shfl_xor_sync(0xffffffffu, psi0, o);
            psj0 += __shfl_xor_sync(0xffffffffu, psj0, o);
            psi1 += __shfl_xor_sync(0xffffffffu, psi1, o);
            psj1 += __shfl_xor_sync(0xffffffffu, psj1, o);
        }
        if ((lane & 3) == 0) {
            atomicAdd(&s_si[lr0], psi0);
            atomicAdd(&s_sj[lr0], psj0);
            atomicAdd(&s_si[lr0 + 8], psi1);
            atomicAdd(&s_sj[lr0 + 8], psj1);
        }
    }
    __syncthreads();
    if (t < 128) {
        int g = block_m + t;
        if (g < M) { g_si[g] = s_si[t]; g_sj[g] = s_sj[t]; }
    }
}

// ---------------- rel_emb dot products (tiny: 500 warps) ---------------------
__global__ void rel_dots_kernel(const float* __restrict__ a,
                                const float* __restrict__ rel_emb) {
    int gw = (blockIdx.x * blockDim.x + threadIdx.x) >> 5;
    int lane = threadIdx.x & 31;
    if (gw >= N_REL) return;
    float4 v = ((const float4*)rel_emb)[(size_t)gw * 32 + lane];
    float4 ar = ((const float4*)(a + 256))[lane];
    float s = v.x * ar.x + v.y * ar.y + v.z * ar.z + v.w * ar.w;
#pragma unroll
    for (int o = 16; o; o >>= 1) s += __shfl_xor_sync(0xffffffffu, s, o);
    if (lane == 0) g_srel[gw] = s;
}

// ---------------- CSR build --------------------------------------------------
#define NE4 (N_EDGES / 4)
#define QTR (NE4 / 4)
__global__ void count_kernel(const int* __restrict__ rows) {
    int i = blockIdx.x * blockDim.x + threadIdx.x;
    if (i >= QTR) return;
    const int4* r4 = (const int4*)rows;
    int4 v0 = r4[i];
    int4 v1 = r4[i + QTR];
    int4 v2 = r4[i + 2 * QTR];
    int4 v3 = r4[i + 3 * QTR];
    atomicAdd(&g_cnt[v0.x], 1); atomicAdd(&g_cnt[v0.y], 1);
    atomicAdd(&g_cnt[v0.z], 1); atomicAdd(&g_cnt[v0.w], 1);
    atomicAdd(&g_cnt[v1.x], 1); atomicAdd(&g_cnt[v1.y], 1);
    atomicAdd(&g_cnt[v1.z], 1); atomicAdd(&g_cnt[v1.w], 1);
    atomicAdd(&g_cnt[v2.x], 1); atomicAdd(&g_cnt[v2.y], 1);
    atomicAdd(&g_cnt[v2.z], 1); atomicAdd(&g_cnt[v2.w], 1);
    atomicAdd(&g_cnt[v3.x], 1); atomicAdd(&g_cnt[v3.y], 1);
    atomicAdd(&g_cnt[v3.z], 1); atomicAdd(&g_cnt[v3.w], 1);
}

// --- 3-phase coalesced scan (replaces the uncoalesced single-block scan) ----
// phase A: per-block sums of 512-element chunks
__global__ void scan_a_kernel() {
    __shared__ int red[SCAN_BLK];
    int b = blockIdx.x, t = threadIdx.x;
    int idx = b * SCAN_BLK + t;
    int v = (idx < N_NODES) ? g_cnt[idx] : 0;
    red[t] = v;
    __syncthreads();
    for (int d = SCAN_BLK / 2; d > 0; d >>= 1) {
        if (t < d) red[t] += red[t + d];
        __syncthreads();
    }
    if (t == 0) g_bsum[b] = red[0];
}
// phase B: exclusive scan of the 98 block sums (one tiny block)
__global__ void scan_b_kernel() {
    __shared__ int sh[128];
    int t = threadIdx.x;
    int v = (t < SCAN_NB) ? g_bsum[t] : 0;
    sh[t] = v;
    __syncthreads();
    for (int d = 1; d < 128; d <<= 1) {
        int u = (t >= d) ? sh[t - d] : 0;
        __syncthreads();
        sh[t] += u;
        __syncthreads();
    }
    if (t < SCAN_NB) g_boff[t] = sh[t] - v;   // exclusive
    if (t == 127) g_off[N_NODES] = sh[127];   // total edges
}
// phase C: local exclusive scan + block offset; writes g_off/g_cur, CLEARS g_cnt
__global__ void scan_c_kernel() {
    __shared__ int sh[SCAN_BLK];
    int b = blockIdx.x, t = threadIdx.x;
    int idx = b * SCAN_BLK + t;
    int v = (idx < N_NODES) ? g_cnt[idx] : 0;
    sh[t] = v;
    __syncthreads();
    for (int d = 1; d < SCAN_BLK; d <<= 1) {
        int u = (t >= d) ? sh[t - d] : 0;
        __syncthreads();
        sh[t] += u;
        __syncthreads();
    }
    if (idx < N_NODES) {
        int off = g_boff[b] + sh[t] - v;      // global exclusive prefix
        g_off[idx] = off;
        g_cur[idx] = off;
        g_cnt[idx] = 0;                       // reset for next replay
    }
}

// topology-only scatter: packs (et<<16)|col into CSR slots (4 edges/thread)
__global__ void scatter_kernel(const int* __restrict__ rows,
                               const int* __restrict__ cols,
                               const int* __restrict__ et) {
    int i = blockIdx.x * blockDim.x + threadIdx.x;
    if (i >= NE4) return;
    int4 r = ((const int4*)rows)[i];
    int4 c = ((const int4*)cols)[i];
    int4 tt = ((const int4*)et)[i];
    int rr[4] = {r.x, r.y, r.z, r.w};
    int cc[4] = {c.x, c.y, c.z, c.w};
    int ee[4] = {tt.x, tt.y, tt.z, tt.w};
#pragma unroll
    for (int j = 0; j < 4; j++) {
        int p = atomicAdd(&g_cur[rr[j]], 1);
        g_pc[p] = ((unsigned)ee[j] << 16) | (unsigned)cc[j];
    }
}

// ---------------- aggregation: R7 form (inline weights) ----------------------
// global max skipped: softmax shift-invariant up to eps, effect <= 1e-9 rel.
__global__ void agg_kernel(float* __restrict__ out) {
    int warp = (blockIdx.x * blockDim.x + threadIdx.x) >> 5;
    int lane = threadIdx.x & 31;
    if (warp >= N_NODES) return;
    int beg = g_off[warp];
    int end = g_off[warp + 1];
    float si_n = g_si[warp];

    float4 acc = make_float4(0.f, 0.f, 0.f, 0.f);
    float sumw = 0.f;

    for (int k = beg; k < end; k += 32) {
        int idx = k + lane;
        unsigned pc = 0u;
        float wv = 0.f;
        if (idx < end) {
            pc = g_pc[idx];
            float x = si_n + g_sj[pc & 0xFFFFu] + g_srel[pc >> 16];
            x = x > 0.f ? x : 0.2f * x;       // leaky_relu
            wv = __expf(x);
        }
        int m = end - k;
        if (m > 32) m = 32;
#pragma unroll 4
        for (int j = 0; j < m; j++) {
            float wj = __shfl_sync(0xffffffffu, wv, j);
            int   cj = (int)(__shfl_sync(0xffffffffu, pc, j) & 0xFFFFu);
            uint2 raw = *((const uint2*)(g_Whh + (size_t)cj * OUT_F) + lane);
            float2 f0 = __half22float2(*(const __half2*)&raw.x);
            float2 f1 = __half22float2(*(const __half2*)&raw.y);
            acc.x = fmaf(wj, f0.x, acc.x);
            acc.y = fmaf(wj, f0.y, acc.y);
            acc.z = fmaf(wj, f1.x, acc.z);
            acc.w = fmaf(wj, f1.y, acc.w);
            sumw += wj;
        }
    }
    float inv = 1.f / (sumw + 1e-10f);
    float4 o;
    o.x = acc.x * inv; o.y = acc.y * inv; o.z = acc.z * inv; o.w = acc.w * inv;
    o.x = o.x > 0.f ? o.x : expf(o.x) - 1.f;
    o.y = o.y > 0.f ? o.y : expf(o.y) - 1.f;
    o.z = o.z > 0.f ? o.z : expf(o.z) - 1.f;
    o.w = o.w > 0.f ? o.w : expf(o.w) - 1.f;
    ((float4*)out)[(size_t)warp * 32 + lane] = o;
}

// ---------------- launch: one side stream; lean graph -------------------------
extern "C" void kernel_launch(void* const* d_in, const int* in_sizes, int n_in,
                              void* d_out, int out_size) {
    const float* h    = (const float*)d_in[0];
    const int*   rows = (const int*)d_in[1];
    const int*   cols = (const int*)d_in[2];
    const int*   et   = (const int*)d_in[3];
    const float* W    = (const float*)d_in[4];
    const float* rel  = (const float*)d_in[5];
    const float* a    = (const float*)d_in[6];
    float* out = (float*)d_out;

    static cudaStream_t s1 = nullptr;
    static cudaEvent_t ef1, ej1;
    if (!s1) {
        cudaStreamCreateWithFlags(&s1, cudaStreamNonBlocking);
        cudaEventCreateWithFlags(&ef1, cudaEventDisableTiming);
        cudaEventCreateWithFlags(&ej1, cudaEventDisableTiming);
    }

    cudaEventRecord(ef1, 0);
    cudaStreamWaitEvent(s1, ef1, 0);

    // launches 1-2: side chain head
    count_kernel<<<(QTR + 255) / 256, 256, 0, s1>>>(rows);
    scan_a_kernel<<<SCAN_NB, SCAN_BLK, 0, s1>>>();

    // launches 3-4: main chain (gemm 4th -> profiled)
    prep_b_kernel<<<(OUT_F * IN_F + 255) / 256, 256>>>(W);
    gemm_kernel<<<(N_NODES + 127) / 128, 256>>>(h, a, N_NODES);

    // launches 5-8: rest of side chain
    scan_b_kernel<<<1, 128, 0, s1>>>();
    scan_c_kernel<<<SCAN_NB, SCAN_BLK, 0, s1>>>();
    scatter_kernel<<<(NE4 + 255) / 256, 256, 0, s1>>>(rows, cols, et);
    rel_dots_kernel<<<(N_REL * 32 + 255) / 256, 256, 0, s1>>>(a, rel);

    // join before agg
    cudaEventRecord(ej1, s1);
    cudaStreamWaitEvent(0, ej1, 0);

    // launch 9: agg
    agg_kernel<<<(N_NODES * 32 + 255) / 256, 256>>>(out);
}

// round 17
// speedup vs baseline: 1.7822x; 1.0459x over previous
#include <cuda_runtime.h>
#include <cuda_fp16.h>
#include <cuda_bf16.h>
#include <cstdint>

#define N_NODES 50000
#define N_EDGES 1600000
#define IN_F    256
#define OUT_F   128
#define N_REL   500

#define SCAN_BLK 512
#define SCAN_NB  ((N_NODES + SCAN_BLK - 1) / SCAN_BLK)   // 98

// ---------------- scratch (device globals; no allocations allowed) ----------
__device__ __half g_Whh[(size_t)N_NODES * OUT_F]; // 12.8 MB fp16 gather table
__device__ float  g_si[N_NODES];
__device__ float  g_sj[N_NODES];
__device__ float  g_srel[N_REL];
__device__ int    g_cnt[N_NODES];                 // zero at load; self-reset
__device__ int    g_bsum[SCAN_NB];
__device__ int    g_boff[SCAN_NB];
__device__ int    g_off[N_NODES + 1];
__device__ int    g_cur[N_NODES];
__device__ unsigned g_pc[N_EDGES];                // (et<<16)|col in CSR order
// W split into bf16 hi/lo planes, stored transposed [n][k]
__device__ __nv_bfloat16 g_Bh[OUT_F * IN_F];
__device__ __nv_bfloat16 g_Bl[OUT_F * IN_F];

// ================= helpers ====================================================
__device__ __forceinline__ uint32_t smem_u32(const void* p) {
    uint32_t a;
    asm("{ .reg .u64 t; cvta.to.shared.u64 t, %1; cvt.u32.u64 %0, t; }"
        : "=r"(a) : "l"(p));
    return a;
}
__device__ __forceinline__ void ldsm4(uint32_t* r, uint32_t a) {
    asm volatile("ldmatrix.sync.aligned.m8n8.x4.shared.b16 {%0,%1,%2,%3}, [%4];"
                 : "=r"(r[0]), "=r"(r[1]), "=r"(r[2]), "=r"(r[3]) : "r"(a));
}
__device__ __forceinline__ void mma_bf16(float* c, const uint32_t* a,
                                         const uint32_t* b) {
    asm volatile(
        "mma.sync.aligned.m16n8k16.row.col.f32.bf16.bf16.f32 "
        "{%0,%1,%2,%3},{%4,%5,%6,%7},{%8,%9},{%0,%1,%2,%3};"
        : "+f"(c[0]), "+f"(c[1]), "+f"(c[2]), "+f"(c[3])
        : "r"(a[0]), "r"(a[1]), "r"(a[2]), "r"(a[3]), "r"(b[0]), "r"(b[1]));
}

// ---------------- prep: split W into bf16 hi/lo, transposed [n][k] -----------
__global__ void prep_b_kernel(const float* __restrict__ W) {
    int id = blockIdx.x * blockDim.x + threadIdx.x;
    if (id >= OUT_F * IN_F) return;
    int n = id >> 8;
    int k = id & 255;
    float v = W[(size_t)k * OUT_F + n];
    __nv_bfloat16 hb = __float2bfloat16_rn(v);
    float lo = v - __bfloat162float(hb);
    g_Bh[id] = hb;
    g_Bl[id] = __float2bfloat16_rn(lo);
}

// ---------------- bf16 tensor-core GEMM (2-split) + fused epilogue -----------
// 2 CTAs/SM (reg cap 128, no reg prefetch): one CTA's fill phase hides under
// the co-resident CTA's MMA phase; waves 2.64 -> 1.32.
#define LDA 40   // bf16 leading dim: 80B rows -> conflict-free LDSM phases
__global__ __launch_bounds__(256, 2) void gemm_kernel(const float* __restrict__ A,
                                                      const float* __restrict__ avec,
                                                      int M) {
    __shared__ __align__(16) __nv_bfloat16 sAh[128 * LDA];
    __shared__ __align__(16) __nv_bfloat16 sAl[128 * LDA];
    __shared__ __align__(16) __nv_bfloat16 sBh[128 * LDA];
    __shared__ __align__(16) __nv_bfloat16 sBl[128 * LDA];
    __shared__ float s_a[256];
    __shared__ float s_si[128], s_sj[128];

    int t = threadIdx.x;
    int lane = t & 31;
    int w = t >> 5;
    int wm = (w & 3) * 32;
    int wn = (w >> 2) * 64;
    int block_m = blockIdx.x * 128;

    if (t < 128) {
        s_si[t] = 0.f; s_sj[t] = 0.f;
        s_a[t] = avec[t]; s_a[128 + t] = avec[128 + t];
    }

    float acc[2][8][4];
#pragma unroll
    for (int i = 0; i < 2; i++)
#pragma unroll
        for (int j = 0; j < 8; j++)
#pragma unroll
            for (int r = 0; r < 4; r++) acc[i][j][r] = 0.f;

    uint32_t bAh = smem_u32(sAh), bAl = smem_u32(sAl);
    uint32_t bBh = smem_u32(sBh), bBl = smem_u32(sBl);
    int r8 = lane & 7, mi = lane >> 3;

    for (int c = 0; c < 8; c++) {           // K chunks of 32
        int k0 = c * 32;
        __syncthreads();                    // smem safe to overwrite
        // ---- fill A: 128 rows x 32 k, fp32 -> bf16 hi/lo ----
#pragma unroll
        for (int s = 0; s < 4; s++) {
            int idx = t + s * 256;          // 1024 float4 slots
            int row = idx >> 3;
            int q = idx & 7;
            int grow = block_m + row;
            if (grow >= M) grow = M - 1;
            float4 v = *(const float4*)(A + (size_t)grow * IN_F + k0 + q * 4);
            float vv[4] = {v.x, v.y, v.z, v.w};
            __nv_bfloat16 hb[4], lb[4];
#pragma unroll
            for (int j = 0; j < 4; j++) {
                hb[j] = __float2bfloat16_rn(vv[j]);
                lb[j] = __float2bfloat16_rn(vv[j] - __bfloat162float(hb[j]));
            }
            *(uint2*)(sAh + row * LDA + q * 4) = *(uint2*)hb;
            *(uint2*)(sAl + row * LDA + q * 4) = *(uint2*)lb;
        }
        // ---- fill B: 128 n x 32 k copies from presplit planes ----
#pragma unroll
        for (int s = 0; s < 2; s++) {
            int idx = t + s * 256;          // 512 uint4 slots per plane
            int n = idx >> 2;
            int q = idx & 3;
            *(uint4*)(sBh + n * LDA + q * 8) =
                *(const uint4*)(g_Bh + (size_t)n * IN_F + k0 + q * 8);
            *(uint4*)(sBl + n * LDA + q * 8) =
                *(const uint4*)(g_Bl + (size_t)n * IN_F + k0 + q * 8);
        }
        __syncthreads();

#pragma unroll
        for (int ks = 0; ks < 2; ks++) {
            uint32_t ahi[2][4], alo[2][4];
#pragma unroll
            for (int ms = 0; ms < 2; ms++) {
                uint32_t off =
                    (uint32_t)((wm + ms * 16 + r8 + (mi & 1) * 8) * LDA +
                               ks * 16 + (mi >> 1) * 8) * 2;
                ldsm4(ahi[ms], bAh + off);
                ldsm4(alo[ms], bAl + off);
            }
            uint32_t bhi[8][2], blo[8][2];
#pragma unroll
            for (int np = 0; np < 4; np++) {
                uint32_t off =
                    (uint32_t)((wn + np * 16 + r8 + (mi >> 1) * 8) * LDA +
                               ks * 16 + (mi & 1) * 8) * 2;
                uint32_t tmp[4];
                ldsm4(tmp, bBh + off);
                bhi[np * 2][0] = tmp[0]; bhi[np * 2][1] = tmp[1];
                bhi[np * 2 + 1][0] = tmp[2]; bhi[np * 2 + 1][1] = tmp[3];
                ldsm4(tmp, bBl + off);
                blo[np * 2][0] = tmp[0]; blo[np * 2][1] = tmp[1];
                blo[np * 2 + 1][0] = tmp[2]; blo[np * 2 + 1][1] = tmp[3];
            }
#pragma unroll
            for (int ns = 0; ns < 8; ns++)
#pragma unroll
                for (int ms = 0; ms < 2; ms++) {
                    mma_bf16(acc[ms][ns], ahi[ms], bhi[ns]);
                    mma_bf16(acc[ms][ns], ahi[ms], blo[ns]);
                    mma_bf16(acc[ms][ns], alo[ms], bhi[ns]);
                }
        }
    }
    __syncthreads();

    // ---- epilogue: fp16 stores + fused attention dots ----
#pragma unroll
    for (int ms = 0; ms < 2; ms++) {
        int lr0 = wm + ms * 16 + (lane >> 2);
        int g0 = block_m + lr0;
        int g1 = g0 + 8;
        float psi0 = 0.f, psj0 = 0.f, psi1 = 0.f, psj1 = 0.f;
#pragma unroll
        for (int ns = 0; ns < 8; ns++) {
            int col0 = wn + ns * 8 + 2 * (lane & 3);
            float* cc = acc[ms][ns];
            float ai0 = s_a[col0], ai1 = s_a[col0 + 1];
            float aj0 = s_a[128 + col0], aj1 = s_a[128 + col0 + 1];
            psi0 += cc[0] * ai0 + cc[1] * ai1;
            psj0 += cc[0] * aj0 + cc[1] * aj1;
            psi1 += cc[2] * ai0 + cc[3] * ai1;
            psj1 += cc[2] * aj0 + cc[3] * aj1;
            if (g0 < M)
                *(__half2*)(g_Whh + (size_t)g0 * OUT_F + col0) =
                    __floats2half2_rn(cc[0], cc[1]);
            if (g1 < M)
                *(__half2*)(g_Whh + (size_t)g1 * OUT_F + col0) =
                    __floats2half2_rn(cc[2], cc[3]);
        }
#pragma unroll
        for (int o = 1; o < 4; o <<= 1) {
            psi0 += __shfl_xor_sync(0xffffffffu, psi0, o);
            psj0 += __shfl_xor_sync(0xffffffffu, psj0, o);
            psi1 += __shfl_xor_sync(0xffffffffu, psi1, o);
            psj1 += __shfl_xor_sync(0xffffffffu, psj1, o);
        }
        if ((lane & 3) == 0) {
            atomicAdd(&s_si[lr0], psi0);
            atomicAdd(&s_sj[lr0], psj0);
            atomicAdd(&s_si[lr0 + 8], psi1);
            atomicAdd(&s_sj[lr0 + 8], psj1);
        }
    }
    __syncthreads();
    if (t < 128) {
        int g = block_m + t;
        if (g < M) { g_si[g] = s_si[t]; g_sj[g] = s_sj[t]; }
    }
}

// ---------------- rel_emb dot products (tiny: 500 warps) ---------------------
__global__ void rel_dots_kernel(const float* __restrict__ a,
                                const float* __restrict__ rel_emb) {
    int gw = (blockIdx.x * blockDim.x + threadIdx.x) >> 5;
    int lane = threadIdx.x & 31;
    if (gw >= N_REL) return;
    float4 v = ((const float4*)rel_emb)[(size_t)gw * 32 + lane];
    float4 ar = ((const float4*)(a + 256))[lane];
    float s = v.x * ar.x + v.y * ar.y + v.z * ar.z + v.w * ar.w;
#pragma unroll
    for (int o = 16; o; o >>= 1) s += __shfl_xor_sync(0xffffffffu, s, o);
    if (lane == 0) g_srel[gw] = s;
}

// ---------------- CSR build --------------------------------------------------
#define NE4 (N_EDGES / 4)
#define QTR (NE4 / 4)
__global__ void count_kernel(const int* __restrict__ rows) {
    int i = blockIdx.x * blockDim.x + threadIdx.x;
    if (i >= QTR) return;
    const int4* r4 = (const int4*)rows;
    int4 v0 = r4[i];
    int4 v1 = r4[i + QTR];
    int4 v2 = r4[i + 2 * QTR];
    int4 v3 = r4[i + 3 * QTR];
    atomicAdd(&g_cnt[v0.x], 1); atomicAdd(&g_cnt[v0.y], 1);
    atomicAdd(&g_cnt[v0.z], 1); atomicAdd(&g_cnt[v0.w], 1);
    atomicAdd(&g_cnt[v1.x], 1); atomicAdd(&g_cnt[v1.y], 1);
    atomicAdd(&g_cnt[v1.z], 1); atomicAdd(&g_cnt[v1.w], 1);
    atomicAdd(&g_cnt[v2.x], 1); atomicAdd(&g_cnt[v2.y], 1);
    atomicAdd(&g_cnt[v2.z], 1); atomicAdd(&g_cnt[v2.w], 1);
    atomicAdd(&g_cnt[v3.x], 1); atomicAdd(&g_cnt[v3.y], 1);
    atomicAdd(&g_cnt[v3.z], 1); atomicAdd(&g_cnt[v3.w], 1);
}

// --- 3-phase coalesced scan ---------------------------------------------------
__global__ void scan_a_kernel() {
    __shared__ int red[SCAN_BLK];
    int b = blockIdx.x, t = threadIdx.x;
    int idx = b * SCAN_BLK + t;
    int v = (idx < N_NODES) ? g_cnt[idx] : 0;
    red[t] = v;
    __syncthreads();
    for (int d = SCAN_BLK / 2; d > 0; d >>= 1) {
        if (t < d) red[t] += red[t + d];
        __syncthreads();
    }
    if (t == 0) g_bsum[b] = red[0];
}
__global__ void scan_b_kernel() {
    __shared__ int sh[128];
    int t = threadIdx.x;
    int v = (t < SCAN_NB) ? g_bsum[t] : 0;
    sh[t] = v;
    __syncthreads();
    for (int d = 1; d < 128; d <<= 1) {
        int u = (t >= d) ? sh[t - d] : 0;
        __syncthreads();
        sh[t] += u;
        __syncthreads();
    }
    if (t < SCAN_NB) g_boff[t] = sh[t] - v;
    if (t == 127) g_off[N_NODES] = sh[127];
}
__global__ void scan_c_kernel() {
    __shared__ int sh[SCAN_BLK];
    int b = blockIdx.x, t = threadIdx.x;
    int idx = b * SCAN_BLK + t;
    int v = (idx < N_NODES) ? g_cnt[idx] : 0;
    sh[t] = v;
    __syncthreads();
    for (int d = 1; d < SCAN_BLK; d <<= 1) {
        int u = (t >= d) ? sh[t - d] : 0;
        __syncthreads();
        sh[t] += u;
        __syncthreads();
    }
    if (idx < N_NODES) {
        int off = g_boff[b] + sh[t] - v;
        g_off[idx] = off;
        g_cur[idx] = off;
        g_cnt[idx] = 0;                       // reset for next replay
    }
}

// topology-only scatter: packs (et<<16)|col into CSR slots (4 edges/thread)
__global__ void scatter_kernel(const int* __restrict__ rows,
                               const int* __restrict__ cols,
                               const int* __restrict__ et) {
    int i = blockIdx.x * blockDim.x + threadIdx.x;
    if (i >= NE4) return;
    int4 r = ((const int4*)rows)[i];
    int4 c = ((const int4*)cols)[i];
    int4 tt = ((const int4*)et)[i];
    int rr[4] = {r.x, r.y, r.z, r.w};
    int cc[4] = {c.x, c.y, c.z, c.w};
    int ee[4] = {tt.x, tt.y, tt.z, tt.w};
#pragma unroll
    for (int j = 0; j < 4; j++) {
        int p = atomicAdd(&g_cur[rr[j]], 1);
        g_pc[p] = ((unsigned)ee[j] << 16) | (unsigned)cc[j];
    }
}

// ---------------- aggregation: R7 form (inline weights) ----------------------
// global max skipped: softmax shift-invariant up to eps, effect <= 1e-9 rel.
__global__ void agg_kernel(float* __restrict__ out) {
    int warp = (blockIdx.x * blockDim.x + threadIdx.x) >> 5;
    int lane = threadIdx.x & 31;
    if (warp >= N_NODES) return;
    int beg = g_off[warp];
    int end = g_off[warp + 1];
    float si_n = g_si[warp];

    float4 acc = make_float4(0.f, 0.f, 0.f, 0.f);
    float sumw = 0.f;

    for (int k = beg; k < end; k += 32) {
        int idx = k + lane;
        unsigned pc = 0u;
        float wv = 0.f;
        if (idx < end) {
            pc = g_pc[idx];
            float x = si_n + g_sj[pc & 0xFFFFu] + g_srel[pc >> 16];
            x = x > 0.f ? x : 0.2f * x;       // leaky_relu
            wv = __expf(x);
        }
        int m = end - k;
        if (m > 32) m = 32;
#pragma unroll 4
        for (int j = 0; j < m; j++) {
            float wj = __shfl_sync(0xffffffffu, wv, j);
            int   cj = (int)(__shfl_sync(0xffffffffu, pc, j) & 0xFFFFu);
            uint2 raw = *((const uint2*)(g_Whh + (size_t)cj * OUT_F) + lane);
            float2 f0 = __half22float2(*(const __half2*)&raw.x);
            float2 f1 = __half22float2(*(const __half2*)&raw.y);
            acc.x = fmaf(wj, f0.x, acc.x);
            acc.y = fmaf(wj, f0.y, acc.y);
            acc.z = fmaf(wj, f1.x, acc.z);
            acc.w = fmaf(wj, f1.y, acc.w);
            sumw += wj;
        }
    }
    float inv = 1.f / (sumw + 1e-10f);
    float4 o;
    o.x = acc.x * inv; o.y = acc.y * inv; o.z = acc.z * inv; o.w = acc.w * inv;
    o.x = o.x > 0.f ? o.x : expf(o.x) - 1.f;
    o.y = o.y > 0.f ? o.y : expf(o.y) - 1.f;
    o.z = o.z > 0.f ? o.z : expf(o.z) - 1.f;
    o.w = o.w > 0.f ? o.w : expf(o.w) - 1.f;
    ((float4*)out)[(size_t)warp * 32 + lane] = o;
}

// ---------------- launch: R16 graph (gemm 4th -> profiled) --------------------
extern "C" void kernel_launch(void* const* d_in, const int* in_sizes, int n_in,
                              void* d_out, int out_size) {
    const float* h    = (const float*)d_in[0];
    const int*   rows = (const int*)d_in[1];
    const int*   cols = (const int*)d_in[2];
    const int*   et   = (const int*)d_in[3];
    const float* W    = (const float*)d_in[4];
    const float* rel  = (const float*)d_in[5];
    const float* a    = (const float*)d_in[6];
    float* out = (float*)d_out;

    static cudaStream_t s1 = nullptr;
    static cudaEvent_t ef1, ej1;
    if (!s1) {
        cudaStreamCreateWithFlags(&s1, cudaStreamNonBlocking);
        cudaEventCreateWithFlags(&ef1, cudaEventDisableTiming);
        cudaEventCreateWithFlags(&ej1, cudaEventDisableTiming);
    }

    cudaEventRecord(ef1, 0);
    cudaStreamWaitEvent(s1, ef1, 0);

    // launches 1-2: side chain head
    count_kernel<<<(QTR + 255) / 256, 256, 0, s1>>>(rows);
    scan_a_kernel<<<SCAN_NB, SCAN_BLK, 0, s1>>>();

    // launches 3-4: main chain (gemm 4th -> profiled)
    prep_b_kernel<<<(OUT_F * IN_F + 255) / 256, 256>>>(W);
    gemm_kernel<<<(N_NODES + 127) / 128, 256>>>(h, a, N_NODES);

    // launches 5-8: rest of side chain
    scan_b_kernel<<<1, 128, 0, s1>>>();
    scan_c_kernel<<<SCAN_NB, SCAN_BLK, 0, s1>>>();
    scatter_kernel<<<(NE4 + 255) / 256, 256, 0, s1>>>(rows, cols, et);
    rel_dots_kernel<<<(N_REL * 32 + 255) / 256, 256, 0, s1>>>(a, rel);

    // join before agg
    cudaEventRecord(ej1, s1);
    cudaStreamWaitEvent(0, ej1, 0);

    // launch 9: agg
    agg_kernel<<<(N_NODES * 32 + 255) / 256, 256>>>(out);
}